// round 5
// baseline (speedup 1.0000x reference)
#include <cuda_runtime.h>
#include <math_constants.h>
#include <cstdint>

// Problem constants
#define BB 4
#define LL 8192
#define DD 768
#define MAXS 100
#define GM (BB*MAXS)   // 400
#define GN DD          // 768
#define GK DD          // 768

// pool config
#define TCH 32
#define PBLK 192

// gemm config
#define SPLITK 4
#define KCHUNK (GK/SPLITK)  // 192
#define KC 32
#define NITER (KCHUNK/KC)   // 6
#define BMT 80
#define BNT 64
#define GT 160

// setup kernel split
#define INIT_BLOCKS 1200                 // 307200 / 256
#define TRANS_BLOCKS (24*24)             // 576

// Scratch (device globals; allocation is forbidden)
__device__ float g_pooledT[GK][GM];          // [768][400]  A^T, k-major
__device__ float g_W2T[GK][GN];              // [768][768]  W2^T, k-major
__device__ float g_part[SPLITK][GM * GN];    // split-K partials

// ---------------------------------------------------------------------------
// helpers
// ---------------------------------------------------------------------------
__device__ __forceinline__ void atomMaxF(float* a, float v) {
    if (v >= 0.0f) atomicMax((int*)a, __float_as_int(v));
    else           atomicMin((unsigned int*)a, __float_as_uint(v));
}

__device__ __forceinline__ void cp_async16(unsigned int smem, const void* gmem) {
    asm volatile("cp.async.cg.shared.global [%0], [%1], 16;\n" :: "r"(smem), "l"(gmem));
}
__device__ __forceinline__ void cp_commit() {
    asm volatile("cp.async.commit_group;\n");
}
template <int N>
__device__ __forceinline__ void cp_wait() {
    asm volatile("cp.async.wait_group %0;\n" :: "n"(N));
}

// packed f32x2 (Blackwell): d = a*b + d  on 2 floats at once
__device__ __forceinline__ void fma2(unsigned long long& d, unsigned long long a,
                                     unsigned long long b) {
    asm("fma.rn.f32x2 %0, %1, %2, %0;" : "+l"(d) : "l"(a), "l"(b));
}
__device__ __forceinline__ unsigned long long dup2(float x) {
    unsigned long long r;
    unsigned int xi = __float_as_uint(x);
    asm("mov.b64 %0, {%1, %1};" : "=l"(r) : "r"(xi));
    return r;
}
__device__ __forceinline__ void unpack2(unsigned long long v, float& lo, float& hi) {
    unsigned int a, b;
    asm("mov.b64 {%0, %1}, %2;" : "=r"(a), "=r"(b) : "l"(v));
    lo = __uint_as_float(a);
    hi = __uint_as_float(b);
}

// ---------------------------------------------------------------------------
// Setup: init pooledT (-inf on valid slots, 0 elsewhere)  +  transpose W2.
// ---------------------------------------------------------------------------
__global__ __launch_bounds__(256) void setup_kernel(const int* __restrict__ ids,
                                                    const float* __restrict__ W2) {
    __shared__ float tile[32][33];
    if (blockIdx.x < INIT_BLOCKS) {
        int i = blockIdx.x * 256 + threadIdx.x;        // over GK*GM = 307200
        int m = i % GM;
        int b = m / MAXS;
        int s = m - b * MAXS;
        int bbmax = ids[b * LL + LL - 1];              // ids sorted -> max id
        ((float*)g_pooledT)[i] = (s < bbmax) ? -CUDART_INF_F : 0.0f;
    } else {
        int bid = blockIdx.x - INIT_BLOCKS;
        int bx = (bid % 24) * 32;   // k base
        int by = (bid / 24) * 32;   // n base
        int x = threadIdx.x & 31;
        int y = threadIdx.x >> 5;   // 0..7
#pragma unroll
        for (int j = 0; j < 32; j += 8)
            tile[y + j][x] = W2[(size_t)(by + y + j) * GK + bx + x];
        __syncthreads();
#pragma unroll
        for (int j = 0; j < 32; j += 8)
            g_W2T[bx + y + j][by + x] = tile[x][y + j];
    }
}

// ---------------------------------------------------------------------------
// Pool: token-parallel segment max. grid (L/TCH, B), 192 threads.
// ---------------------------------------------------------------------------
__global__ __launch_bounds__(PBLK) void pool_kernel(const float* __restrict__ wf,
                                                    const int* __restrict__ ids) {
    __shared__ int sid[TCH];
    const int b = blockIdx.y;
    const int c0 = blockIdx.x * TCH;
    const int tid = threadIdx.x;
    if (tid < TCH) sid[tid] = ids[b * LL + c0 + tid];
    __syncthreads();

    const float4* __restrict__ base =
        (const float4*)(wf + ((size_t)b * LL + c0) * DD) + tid;   // row stride DD/4

    float4 run = make_float4(-CUDART_INF_F, -CUDART_INF_F, -CUDART_INF_F, -CUDART_INF_F);
    int cur = -1;
    const int d0 = tid * 4;

#pragma unroll
    for (int t0 = 0; t0 < TCH; t0 += 8) {
        float4 v[8];
#pragma unroll
        for (int j = 0; j < 8; ++j)
            v[j] = __ldcs(base + (size_t)(t0 + j) * (DD / 4));
#pragma unroll
        for (int j = 0; j < 8; ++j) {
            int id = sid[t0 + j];
            if (id != cur) {
                if (cur > 0) {
                    int m = b * MAXS + cur - 1;
                    atomMaxF(&g_pooledT[d0 + 0][m], run.x);
                    atomMaxF(&g_pooledT[d0 + 1][m], run.y);
                    atomMaxF(&g_pooledT[d0 + 2][m], run.z);
                    atomMaxF(&g_pooledT[d0 + 3][m], run.w);
                }
                cur = id;
                run = make_float4(-CUDART_INF_F, -CUDART_INF_F, -CUDART_INF_F, -CUDART_INF_F);
            }
            if (id > 0) {
                run.x = fmaxf(run.x, v[j].x);
                run.y = fmaxf(run.y, v[j].y);
                run.z = fmaxf(run.z, v[j].z);
                run.w = fmaxf(run.w, v[j].w);
            }
        }
    }
    if (cur > 0) {
        int m = b * MAXS + cur - 1;
        atomMaxF(&g_pooledT[d0 + 0][m], run.x);
        atomMaxF(&g_pooledT[d0 + 1][m], run.y);
        atomMaxF(&g_pooledT[d0 + 2][m], run.z);
        atomMaxF(&g_pooledT[d0 + 3][m], run.w);
    }
}

// ---------------------------------------------------------------------------
// GEMM (FFMA2): part[kz][m][n] = sum_{k in chunk kz} AT[k][m] * W2T[k][n]
// grid (5, 12, 4) = 240 blocks. 160 threads = 5 warps.
// Thread micro-tile 4m x 8n; m packed in f32x2 pairs (LDS.64 from As),
// b duplicated via mov.b64. cp.async double-buffered smem pipeline.
// ---------------------------------------------------------------------------
__global__ __launch_bounds__(GT) void gemm_kernel() {
    __shared__ float As[2][KC * BMT];   // 10.24 KB each
    __shared__ float Bs[2][KC * BNT];   // 8 KB each

    const int mb = blockIdx.x * BMT;
    const int nb = blockIdx.y * BNT;
    const int kbase = blockIdx.z * KCHUNK;

    const int tid = threadIdx.x;
    const int tx = tid & 7;     // 0..7  -> n0 = tx*8
    const int ty = tid >> 3;    // 0..19 -> m0 = ty*4
    const int m0 = ty * 4;
    const int n0 = tx * 8;

    const unsigned int sA0 = (unsigned int)__cvta_generic_to_shared(&As[0][0]);
    const unsigned int sB0 = (unsigned int)__cvta_generic_to_shared(&Bs[0][0]);

    auto load_tile = [&](int buf, int kt) {
        const unsigned int sa = sA0 + (unsigned int)(buf * KC * BMT * 4);
        const unsigned int sb = sB0 + (unsigned int)(buf * KC * BNT * 4);
        // A: KC*BMT/4 = 640 float4, 4 per thread (rows of 20 float4)
#pragma unroll
        for (int j = 0; j < 4; ++j) {
            int i = tid + j * GT;           // 0..639
            int k = i / 20;
            int m4 = i - k * 20;
            cp_async16(sa + (unsigned int)((k * BMT + m4 * 4) * 4),
                       &g_pooledT[kbase + kt + k][mb + m4 * 4]);
        }
        // B: KC*BNT/4 = 512 float4 (rows of 16 float4)
#pragma unroll
        for (int j = 0; j < 4; ++j) {
            int i = tid + j * GT;
            if (i < KC * BNT / 4) {
                int k = i >> 4;
                int n4 = i & 15;
                cp_async16(sb + (unsigned int)((k * BNT + n4 * 4) * 4),
                           &g_W2T[kbase + kt + k][nb + n4 * 4]);
            }
        }
        cp_commit();
    };

    unsigned long long acc2[2][8];
#pragma unroll
    for (int p = 0; p < 2; ++p)
#pragma unroll
        for (int j = 0; j < 8; ++j) acc2[p][j] = 0ull;

    load_tile(0, 0);

    for (int it = 0; it < NITER; ++it) {
        cp_wait<0>();
        __syncthreads();

        if (it + 1 < NITER) load_tile((it + 1) & 1, (it + 1) * KC);

        const float* __restrict__ Ab = &As[it & 1][0];
        const float* __restrict__ Bb = &Bs[it & 1][0];
#pragma unroll
        for (int k = 0; k < KC; ++k) {
            const unsigned long long* Ap =
                (const unsigned long long*)(Ab + k * BMT + m0);
            unsigned long long a01 = Ap[0];   // (m0, m0+1)
            unsigned long long a23 = Ap[1];   // (m0+2, m0+3)
            float4 bl = *(const float4*)&Bb[k * BNT + n0];
            float4 bh = *(const float4*)&Bb[k * BNT + n0 + 4];
            unsigned long long bd[8];
            bd[0] = dup2(bl.x); bd[1] = dup2(bl.y); bd[2] = dup2(bl.z); bd[3] = dup2(bl.w);
            bd[4] = dup2(bh.x); bd[5] = dup2(bh.y); bd[6] = dup2(bh.z); bd[7] = dup2(bh.w);
#pragma unroll
            for (int j = 0; j < 8; ++j) {
                fma2(acc2[0][j], a01, bd[j]);
                fma2(acc2[1][j], a23, bd[j]);
            }
        }
        __syncthreads();
    }

    float* __restrict__ part = g_part[blockIdx.z];
#pragma unroll
    for (int p = 0; p < 2; ++p) {
        float lo[8], hi[8];
#pragma unroll
        for (int j = 0; j < 8; ++j) unpack2(acc2[p][j], lo[j], hi[j]);
        int mA = mb + m0 + 2 * p;
        float4 s0 = make_float4(lo[0], lo[1], lo[2], lo[3]);
        float4 s1 = make_float4(lo[4], lo[5], lo[6], lo[7]);
        float4 s2 = make_float4(hi[0], hi[1], hi[2], hi[3]);
        float4 s3 = make_float4(hi[4], hi[5], hi[6], hi[7]);
        *(float4*)&part[(size_t)mA * GN + nb + n0]           = s0;
        *(float4*)&part[(size_t)mA * GN + nb + n0 + 4]       = s1;
        *(float4*)&part[(size_t)(mA + 1) * GN + nb + n0]     = s2;
        *(float4*)&part[(size_t)(mA + 1) * GN + nb + n0 + 4] = s3;
    }
}

// ---------------------------------------------------------------------------
// Combine split-K partials + bias. 2 float4 per thread, 10 loads in flight.
// ---------------------------------------------------------------------------
__global__ __launch_bounds__(256) void combine_kernel(const float* __restrict__ b2,
                                                      float* __restrict__ out) {
    int i0 = blockIdx.x * 512 + threadIdx.x;      // over GM*GN/4 = 76800
    int i1 = i0 + 256;
    float4 r0 = ((const float4*)b2)[i0 % (GN / 4)];
    float4 r1 = ((const float4*)b2)[i1 % (GN / 4)];
#pragma unroll
    for (int z = 0; z < SPLITK; ++z) {
        float4 p0 = ((const float4*)g_part[z])[i0];
        float4 p1 = ((const float4*)g_part[z])[i1];
        r0.x += p0.x; r0.y += p0.y; r0.z += p0.z; r0.w += p0.w;
        r1.x += p1.x; r1.y += p1.y; r1.z += p1.z; r1.w += p1.w;
    }
    ((float4*)out)[i0] = r0;
    ((float4*)out)[i1] = r1;
}

// ---------------------------------------------------------------------------
extern "C" void kernel_launch(void* const* d_in, const int* in_sizes, int n_in,
                              void* d_out, int out_size) {
    const float* wf  = (const float*)d_in[0];   // [4,8192,768] f32
    const int*   ids = (const int*)d_in[1];     // [4,8192] i32
    const float* W2  = (const float*)d_in[2];   // [768,768] f32
    const float* b2  = (const float*)d_in[3];   // [768] f32
    float* out = (float*)d_out;                 // [4,100,768] f32

    setup_kernel<<<INIT_BLOCKS + TRANS_BLOCKS, 256>>>(ids, W2);
    pool_kernel<<<dim3(LL / TCH, BB), PBLK>>>(wf, ids);
    gemm_kernel<<<dim3(GM / BMT, GN / BNT, SPLITK), GT>>>();
    combine_kernel<<<150, 256>>>(b2, out);
}

// round 6
// speedup vs baseline: 1.0481x; 1.0481x over previous
#include <cuda_runtime.h>
#include <math_constants.h>
#include <cstdint>

// Problem constants
#define BB 4
#define LL 8192
#define DD 768
#define MAXS 100
#define GM (BB*MAXS)   // 400
#define GN DD          // 768
#define GK DD          // 768

// pool config
#define TCH 32
#define PBLK 192

// gemm config (R4-winning shape)
#define SPLITK 6
#define KCHUNK (GK/SPLITK)  // 128
#define KC 32
#define NITER (KCHUNK/KC)   // 4
#define BMT 100
#define BNT 32
#define GT 160
#define NTILES ((GM/BMT)*(GN/BNT))   // 4*24 = 96

// setup kernel split
#define INIT_BLOCKS 1200                 // 307200 / 256
#define TRANS_BLOCKS (24*24)             // 576

// Scratch (device globals; allocation is forbidden)
__device__ float g_pooledT[GK][GM];          // [768][400]  A^T, k-major
__device__ float g_W2T[GK][GN];              // [768][768]  W2^T, k-major
__device__ float g_part[SPLITK][GM * GN];    // split-K partials
__device__ int   g_ticket[NTILES];           // per-tile completion counters

// ---------------------------------------------------------------------------
// helpers
// ---------------------------------------------------------------------------
__device__ __forceinline__ void atomMaxF(float* a, float v) {
    if (v >= 0.0f) atomicMax((int*)a, __float_as_int(v));
    else           atomicMin((unsigned int*)a, __float_as_uint(v));
}

__device__ __forceinline__ void cp_async16(unsigned int smem, const void* gmem) {
    asm volatile("cp.async.cg.shared.global [%0], [%1], 16;\n" :: "r"(smem), "l"(gmem));
}
__device__ __forceinline__ void cp_commit() {
    asm volatile("cp.async.commit_group;\n");
}
template <int N>
__device__ __forceinline__ void cp_wait() {
    asm volatile("cp.async.wait_group %0;\n" :: "n"(N));
}

// ---------------------------------------------------------------------------
// Setup: init pooledT (-inf on valid slots, 0 elsewhere) + transpose W2 +
// re-zero split-K tickets (needed for graph replays).
// ---------------------------------------------------------------------------
__global__ __launch_bounds__(256) void setup_kernel(const int* __restrict__ ids,
                                                    const float* __restrict__ W2) {
    __shared__ float tile[32][33];
    if (blockIdx.x < INIT_BLOCKS) {
        if (blockIdx.x == 0 && threadIdx.x < NTILES) g_ticket[threadIdx.x] = 0;
        int i = blockIdx.x * 256 + threadIdx.x;        // over GK*GM = 307200
        int m = i % GM;
        int b = m / MAXS;
        int s = m - b * MAXS;
        int bbmax = ids[b * LL + LL - 1];              // ids sorted -> max id
        ((float*)g_pooledT)[i] = (s < bbmax) ? -CUDART_INF_F : 0.0f;
    } else {
        int bid = blockIdx.x - INIT_BLOCKS;
        int bx = (bid % 24) * 32;   // k base
        int by = (bid / 24) * 32;   // n base
        int x = threadIdx.x & 31;
        int y = threadIdx.x >> 5;   // 0..7
#pragma unroll
        for (int j = 0; j < 32; j += 8)
            tile[y + j][x] = W2[(size_t)(by + y + j) * GK + bx + x];
        __syncthreads();
#pragma unroll
        for (int j = 0; j < 32; j += 8)
            g_W2T[bx + y + j][by + x] = tile[x][y + j];
    }
}

// ---------------------------------------------------------------------------
// Pool: token-parallel segment max. grid (L/TCH, B), 192 threads.
// Thread owns float4 column; 8 LDG.128 in flight; streaming loads (__ldcs).
// ids sorted -> flushes rare & warp-uniform; exact float atomics.
// ---------------------------------------------------------------------------
__global__ __launch_bounds__(PBLK) void pool_kernel(const float* __restrict__ wf,
                                                    const int* __restrict__ ids) {
    __shared__ int sid[TCH];
    const int b = blockIdx.y;
    const int c0 = blockIdx.x * TCH;
    const int tid = threadIdx.x;
    if (tid < TCH) sid[tid] = ids[b * LL + c0 + tid];
    __syncthreads();

    const float4* __restrict__ base =
        (const float4*)(wf + ((size_t)b * LL + c0) * DD) + tid;   // row stride DD/4

    float4 run = make_float4(-CUDART_INF_F, -CUDART_INF_F, -CUDART_INF_F, -CUDART_INF_F);
    int cur = -1;
    const int d0 = tid * 4;

#pragma unroll
    for (int t0 = 0; t0 < TCH; t0 += 8) {
        float4 v[8];
#pragma unroll
        for (int j = 0; j < 8; ++j)
            v[j] = __ldcs(base + (size_t)(t0 + j) * (DD / 4));
#pragma unroll
        for (int j = 0; j < 8; ++j) {
            int id = sid[t0 + j];
            if (id != cur) {
                if (cur > 0) {
                    int m = b * MAXS + cur - 1;
                    atomMaxF(&g_pooledT[d0 + 0][m], run.x);
                    atomMaxF(&g_pooledT[d0 + 1][m], run.y);
                    atomMaxF(&g_pooledT[d0 + 2][m], run.z);
                    atomMaxF(&g_pooledT[d0 + 3][m], run.w);
                }
                cur = id;
                run = make_float4(-CUDART_INF_F, -CUDART_INF_F, -CUDART_INF_F, -CUDART_INF_F);
            }
            if (id > 0) {
                run.x = fmaxf(run.x, v[j].x);
                run.y = fmaxf(run.y, v[j].y);
                run.z = fmaxf(run.z, v[j].z);
                run.w = fmaxf(run.w, v[j].w);
            }
        }
    }
    if (cur > 0) {
        int m = b * MAXS + cur - 1;
        atomMaxF(&g_pooledT[d0 + 0][m], run.x);
        atomMaxF(&g_pooledT[d0 + 1][m], run.y);
        atomMaxF(&g_pooledT[d0 + 2][m], run.z);
        atomMaxF(&g_pooledT[d0 + 3][m], run.w);
    }
}

// ---------------------------------------------------------------------------
// GEMM + fused split-K reduction.
// part[kz][m][n] = sum_{k in chunk kz} AT[k][m] * W2T[k][n]
// grid (4, 24, 6) = 576 blocks. 160 threads = 5 warps, micro 5x4, scalar FFMA.
// Last z-block per tile (ticket) re-reads all 6 partials in fixed z order,
// adds bias, writes out. Deterministic; no separate combine launch.
// ---------------------------------------------------------------------------
__global__ __launch_bounds__(GT) void gemm_kernel(const float* __restrict__ b2,
                                                  float* __restrict__ out) {
    __shared__ float As[2][KC * BMT];   // 12.8 KB each
    __shared__ float Bs[2][KC * BNT];   // 4.0 KB each
    __shared__ int s_ticket;

    const int mb = blockIdx.x * BMT;
    const int nb = blockIdx.y * BNT;
    const int kbase = blockIdx.z * KCHUNK;
    const int tileid = blockIdx.x * (GN / BNT) + blockIdx.y;

    const int tid = threadIdx.x;
    const int tx = tid & 7;     // n micro (x4)
    const int ty = tid >> 3;    // m micro (x5)
    const int ty5 = ty * 5;
    const int tx4 = tx * 4;

    const unsigned int sA0 = (unsigned int)__cvta_generic_to_shared(&As[0][0]);
    const unsigned int sB0 = (unsigned int)__cvta_generic_to_shared(&Bs[0][0]);

    auto load_tile = [&](int buf, int kt) {
        const unsigned int sa = sA0 + (unsigned int)(buf * KC * BMT * 4);
        const unsigned int sb = sB0 + (unsigned int)(buf * KC * BNT * 4);
        // A: KC*BMT/4 = 800 float4, 5 per thread (rows of 25 float4)
#pragma unroll
        for (int j = 0; j < 5; ++j) {
            int i = tid + j * GT;           // 0..799
            int k = i / 25;
            int m4 = i - k * 25;
            cp_async16(sa + (unsigned int)((k * BMT + m4 * 4) * 4),
                       &g_pooledT[kbase + kt + k][mb + m4 * 4]);
        }
        // B: KC*BNT/4 = 256 float4
        for (int i = tid; i < KC * BNT / 4; i += GT) {
            int k = i >> 3;
            int n4 = i & 7;
            cp_async16(sb + (unsigned int)((k * BNT + n4 * 4) * 4),
                       &g_W2T[kbase + kt + k][nb + n4 * 4]);
        }
        cp_commit();
    };

    float acc[5][4];
#pragma unroll
    for (int i = 0; i < 5; ++i)
#pragma unroll
        for (int j = 0; j < 4; ++j) acc[i][j] = 0.0f;

    load_tile(0, 0);

    for (int it = 0; it < NITER; ++it) {
        cp_wait<0>();
        __syncthreads();

        if (it + 1 < NITER) load_tile((it + 1) & 1, (it + 1) * KC);

        const float* __restrict__ Ab = &As[it & 1][0];
        const float* __restrict__ Bb = &Bs[it & 1][0];
#pragma unroll
        for (int k = 0; k < KC; ++k) {
            float a0 = Ab[k * BMT + ty5 + 0];
            float a1 = Ab[k * BMT + ty5 + 1];
            float a2 = Ab[k * BMT + ty5 + 2];
            float a3 = Ab[k * BMT + ty5 + 3];
            float a4 = Ab[k * BMT + ty5 + 4];
            float4 b4 = *(const float4*)&Bb[k * BNT + tx4];
            acc[0][0] = fmaf(a0, b4.x, acc[0][0]); acc[0][1] = fmaf(a0, b4.y, acc[0][1]);
            acc[0][2] = fmaf(a0, b4.z, acc[0][2]); acc[0][3] = fmaf(a0, b4.w, acc[0][3]);
            acc[1][0] = fmaf(a1, b4.x, acc[1][0]); acc[1][1] = fmaf(a1, b4.y, acc[1][1]);
            acc[1][2] = fmaf(a1, b4.z, acc[1][2]); acc[1][3] = fmaf(a1, b4.w, acc[1][3]);
            acc[2][0] = fmaf(a2, b4.x, acc[2][0]); acc[2][1] = fmaf(a2, b4.y, acc[2][1]);
            acc[2][2] = fmaf(a2, b4.z, acc[2][2]); acc[2][3] = fmaf(a2, b4.w, acc[2][3]);
            acc[3][0] = fmaf(a3, b4.x, acc[3][0]); acc[3][1] = fmaf(a3, b4.y, acc[3][1]);
            acc[3][2] = fmaf(a3, b4.z, acc[3][2]); acc[3][3] = fmaf(a3, b4.w, acc[3][3]);
            acc[4][0] = fmaf(a4, b4.x, acc[4][0]); acc[4][1] = fmaf(a4, b4.y, acc[4][1]);
            acc[4][2] = fmaf(a4, b4.z, acc[4][2]); acc[4][3] = fmaf(a4, b4.w, acc[4][3]);
        }
        __syncthreads();
    }

    // store partial for this z
    float* __restrict__ part = g_part[blockIdx.z];
#pragma unroll
    for (int i = 0; i < 5; ++i) {
        int m = mb + ty5 + i;
        float4 st = make_float4(acc[i][0], acc[i][1], acc[i][2], acc[i][3]);
        *(float4*)&part[(size_t)m * GN + nb + tx4] = st;
    }

    // ticket: last block of this tile reduces all SPLITK partials (fixed order)
    __threadfence();
    if (tid == 0) s_ticket = atomicAdd(&g_ticket[tileid], 1);
    __syncthreads();
    if (s_ticket == SPLITK - 1) {
        __threadfence();
        float4 bias = *(const float4*)&b2[nb + tx4];
#pragma unroll
        for (int i = 0; i < 5; ++i) {
            int m = mb + ty5 + i;
            size_t off = (size_t)m * GN + nb + tx4;
            float4 r = bias;
#pragma unroll
            for (int z = 0; z < SPLITK; ++z) {
                float4 p = *(const float4*)&g_part[z][off];
                r.x += p.x; r.y += p.y; r.z += p.z; r.w += p.w;
            }
            *(float4*)&out[off] = r;
        }
    }
}

// ---------------------------------------------------------------------------
extern "C" void kernel_launch(void* const* d_in, const int* in_sizes, int n_in,
                              void* d_out, int out_size) {
    const float* wf  = (const float*)d_in[0];   // [4,8192,768] f32
    const int*   ids = (const int*)d_in[1];     // [4,8192] i32
    const float* W2  = (const float*)d_in[2];   // [768,768] f32
    const float* b2  = (const float*)d_in[3];   // [768] f32
    float* out = (float*)d_out;                 // [4,100,768] f32

    setup_kernel<<<INIT_BLOCKS + TRANS_BLOCKS, 256>>>(ids, W2);
    pool_kernel<<<dim3(LL / TCH, BB), PBLK>>>(wf, ids);
    gemm_kernel<<<dim3(GM / BMT, GN / BNT, SPLITK), GT>>>(b2, out);
}

// round 7
// speedup vs baseline: 1.1004x; 1.0498x over previous
#include <cuda_runtime.h>
#include <math_constants.h>
#include <cstdint>

// Problem constants
#define BB 4
#define LL 8192
#define DD 768
#define MAXS 100
#define GM (BB*MAXS)   // 400
#define GN DD          // 768
#define GK DD          // 768

// pool config
#define TCH 32
#define PBLK 192
#define POOL_BLOCKS ((LL/TCH)*BB)        // 1024
#define TRANS_BLOCKS (24*24)             // 576

// gemm config (R4-winning shape)
#define SPLITK 6
#define KCHUNK (GK/SPLITK)  // 128
#define KC 32
#define NITER (KCHUNK/KC)   // 4
#define BMT 100
#define BNT 32
#define GT 160

// Scratch (device globals; allocation is forbidden)
__device__ float g_pooledT[GK][GM];          // [768][400]  A^T, k-major
__device__ float g_W2T[GK][GN];              // [768][768]  W2^T, k-major
__device__ float g_part[SPLITK][GM * GN];    // split-K partials

// ---------------------------------------------------------------------------
// helpers
// ---------------------------------------------------------------------------
__device__ __forceinline__ void atomMaxF(float* a, float v) {
    if (v >= 0.0f) atomicMax((int*)a, __float_as_int(v));
    else           atomicMin((unsigned int*)a, __float_as_uint(v));
}

__device__ __forceinline__ void cp_async16(unsigned int smem, const void* gmem) {
    asm volatile("cp.async.cg.shared.global [%0], [%1], 16;\n" :: "r"(smem), "l"(gmem));
}
__device__ __forceinline__ void cp_commit() {
    asm volatile("cp.async.commit_group;\n");
}
template <int N>
__device__ __forceinline__ void cp_wait() {
    asm volatile("cp.async.wait_group %0;\n" :: "n"(N));
}

// ---------------------------------------------------------------------------
// Init: g_pooledT = -inf on valid slots (s < bb[b]), 0 elsewhere. float4.
// 300 blocks x 256 threads, one float4 each (76800 total).
// ---------------------------------------------------------------------------
__global__ __launch_bounds__(256) void init_kernel(const int* __restrict__ ids) {
    int i4 = blockIdx.x * 256 + threadIdx.x;       // 0..76799
    int flat = i4 * 4;                              // over GK*GM
    int m = flat % GM;                              // multiple of 4, same k row
    int b = m / MAXS;
    int s = m - b * MAXS;                           // s..s+3 same batch (100%4 ok)
    int bbmax = __ldg(&ids[b * LL + LL - 1]);       // ids sorted -> max id
    float4 v;
    v.x = (s + 0 < bbmax) ? -CUDART_INF_F : 0.0f;
    v.y = (s + 1 < bbmax) ? -CUDART_INF_F : 0.0f;
    v.z = (s + 2 < bbmax) ? -CUDART_INF_F : 0.0f;
    v.w = (s + 3 < bbmax) ? -CUDART_INF_F : 0.0f;
    ((float4*)g_pooledT)[i4] = v;
}

// ---------------------------------------------------------------------------
// Pool + W2 transpose fused in one launch (independent jobs, overlap).
// Blocks [0, TRANS_BLOCKS): transpose W2[n][k] -> g_W2T[k][n] (32x32 tiles).
// Blocks [TRANS_BLOCKS, +POOL_BLOCKS): token-parallel segment max.
// ---------------------------------------------------------------------------
__global__ __launch_bounds__(PBLK) void pool_kernel(const float* __restrict__ wf,
                                                    const int* __restrict__ ids,
                                                    const float* __restrict__ W2) {
    __shared__ float tile[32][33];
    __shared__ int sid[TCH];
    const int tid = threadIdx.x;

    if (blockIdx.x < TRANS_BLOCKS) {
        int bid = blockIdx.x;
        int bx = (bid % 24) * 32;   // k base
        int by = (bid / 24) * 32;   // n base
        int x = tid & 31;
        int y = tid >> 5;           // 0..5 (192 threads)
#pragma unroll
        for (int j = 0; j < 6; ++j) {
            int row = y + j * 6;
            if (row < 32)
                tile[row][x] = W2[(size_t)(by + row) * GK + bx + x];
        }
        __syncthreads();
#pragma unroll
        for (int j = 0; j < 6; ++j) {
            int row = y + j * 6;
            if (row < 32)
                g_W2T[bx + row][by + x] = tile[x][row];
        }
        return;
    }

    const int pb = blockIdx.x - TRANS_BLOCKS;
    const int b = pb >> 8;                   // LL/TCH = 256 chunks per batch
    const int c0 = (pb & 255) * TCH;
    if (tid < TCH) sid[tid] = ids[b * LL + c0 + tid];
    __syncthreads();

    const float4* __restrict__ base =
        (const float4*)(wf + ((size_t)b * LL + c0) * DD) + tid;   // row stride DD/4

    float4 run = make_float4(-CUDART_INF_F, -CUDART_INF_F, -CUDART_INF_F, -CUDART_INF_F);
    int cur = -1;
    const int d0 = tid * 4;

#pragma unroll
    for (int t0 = 0; t0 < TCH; t0 += 8) {
        float4 v[8];
#pragma unroll
        for (int j = 0; j < 8; ++j)
            v[j] = __ldcs(base + (size_t)(t0 + j) * (DD / 4));
#pragma unroll
        for (int j = 0; j < 8; ++j) {
            int id = sid[t0 + j];
            if (id != cur) {
                if (cur > 0) {
                    int m = b * MAXS + cur - 1;
                    atomMaxF(&g_pooledT[d0 + 0][m], run.x);
                    atomMaxF(&g_pooledT[d0 + 1][m], run.y);
                    atomMaxF(&g_pooledT[d0 + 2][m], run.z);
                    atomMaxF(&g_pooledT[d0 + 3][m], run.w);
                }
                cur = id;
                run = make_float4(-CUDART_INF_F, -CUDART_INF_F, -CUDART_INF_F, -CUDART_INF_F);
            }
            if (id > 0) {
                run.x = fmaxf(run.x, v[j].x);
                run.y = fmaxf(run.y, v[j].y);
                run.z = fmaxf(run.z, v[j].z);
                run.w = fmaxf(run.w, v[j].w);
            }
        }
    }
    if (cur > 0) {
        int m = b * MAXS + cur - 1;
        atomMaxF(&g_pooledT[d0 + 0][m], run.x);
        atomMaxF(&g_pooledT[d0 + 1][m], run.y);
        atomMaxF(&g_pooledT[d0 + 2][m], run.z);
        atomMaxF(&g_pooledT[d0 + 3][m], run.w);
    }
}

// ---------------------------------------------------------------------------
// GEMM: part[kz][m][n] = sum_{k in chunk kz} AT[k][m] * W2T[k][n]
// grid (4, 24, 6) = 576 blocks. 160 threads = 5 warps, micro 5x4, scalar FFMA.
// cp.async double-buffered smem pipeline. (Exact R4-winning kernel.)
// ---------------------------------------------------------------------------
__global__ __launch_bounds__(GT) void gemm_kernel() {
    __shared__ float As[2][KC * BMT];   // 12.8 KB each
    __shared__ float Bs[2][KC * BNT];   // 4.0 KB each

    const int mb = blockIdx.x * BMT;
    const int nb = blockIdx.y * BNT;
    const int kbase = blockIdx.z * KCHUNK;

    const int tid = threadIdx.x;
    const int tx = tid & 7;     // n micro (x4)
    const int ty = tid >> 3;    // m micro (x5)
    const int ty5 = ty * 5;
    const int tx4 = tx * 4;

    const unsigned int sA0 = (unsigned int)__cvta_generic_to_shared(&As[0][0]);
    const unsigned int sB0 = (unsigned int)__cvta_generic_to_shared(&Bs[0][0]);

    auto load_tile = [&](int buf, int kt) {
        const unsigned int sa = sA0 + (unsigned int)(buf * KC * BMT * 4);
        const unsigned int sb = sB0 + (unsigned int)(buf * KC * BNT * 4);
        // A: KC*BMT/4 = 800 float4, 5 per thread (rows of 25 float4)
#pragma unroll
        for (int j = 0; j < 5; ++j) {
            int i = tid + j * GT;           // 0..799
            int k = i / 25;
            int m4 = i - k * 25;
            cp_async16(sa + (unsigned int)((k * BMT + m4 * 4) * 4),
                       &g_pooledT[kbase + kt + k][mb + m4 * 4]);
        }
        // B: KC*BNT/4 = 256 float4
        for (int i = tid; i < KC * BNT / 4; i += GT) {
            int k = i >> 3;
            int n4 = i & 7;
            cp_async16(sb + (unsigned int)((k * BNT + n4 * 4) * 4),
                       &g_W2T[kbase + kt + k][nb + n4 * 4]);
        }
        cp_commit();
    };

    float acc[5][4];
#pragma unroll
    for (int i = 0; i < 5; ++i)
#pragma unroll
        for (int j = 0; j < 4; ++j) acc[i][j] = 0.0f;

    load_tile(0, 0);

    for (int it = 0; it < NITER; ++it) {
        cp_wait<0>();
        __syncthreads();

        if (it + 1 < NITER) load_tile((it + 1) & 1, (it + 1) * KC);

        const float* __restrict__ Ab = &As[it & 1][0];
        const float* __restrict__ Bb = &Bs[it & 1][0];
#pragma unroll
        for (int k = 0; k < KC; ++k) {
            float a0 = Ab[k * BMT + ty5 + 0];
            float a1 = Ab[k * BMT + ty5 + 1];
            float a2 = Ab[k * BMT + ty5 + 2];
            float a3 = Ab[k * BMT + ty5 + 3];
            float a4 = Ab[k * BMT + ty5 + 4];
            float4 b4 = *(const float4*)&Bb[k * BNT + tx4];
            acc[0][0] = fmaf(a0, b4.x, acc[0][0]); acc[0][1] = fmaf(a0, b4.y, acc[0][1]);
            acc[0][2] = fmaf(a0, b4.z, acc[0][2]); acc[0][3] = fmaf(a0, b4.w, acc[0][3]);
            acc[1][0] = fmaf(a1, b4.x, acc[1][0]); acc[1][1] = fmaf(a1, b4.y, acc[1][1]);
            acc[1][2] = fmaf(a1, b4.z, acc[1][2]); acc[1][3] = fmaf(a1, b4.w, acc[1][3]);
            acc[2][0] = fmaf(a2, b4.x, acc[2][0]); acc[2][1] = fmaf(a2, b4.y, acc[2][1]);
            acc[2][2] = fmaf(a2, b4.z, acc[2][2]); acc[2][3] = fmaf(a2, b4.w, acc[2][3]);
            acc[3][0] = fmaf(a3, b4.x, acc[3][0]); acc[3][1] = fmaf(a3, b4.y, acc[3][1]);
            acc[3][2] = fmaf(a3, b4.z, acc[3][2]); acc[3][3] = fmaf(a3, b4.w, acc[3][3]);
            acc[4][0] = fmaf(a4, b4.x, acc[4][0]); acc[4][1] = fmaf(a4, b4.y, acc[4][1]);
            acc[4][2] = fmaf(a4, b4.z, acc[4][2]); acc[4][3] = fmaf(a4, b4.w, acc[4][3]);
        }
        __syncthreads();
    }

    float* __restrict__ part = g_part[blockIdx.z];
#pragma unroll
    for (int i = 0; i < 5; ++i) {
        int m = mb + ty5 + i;
        float4 st = make_float4(acc[i][0], acc[i][1], acc[i][2], acc[i][3]);
        *(float4*)&part[(size_t)m * GN + nb + tx4] = st;
    }
}

// ---------------------------------------------------------------------------
// Combine split-K partials + bias (float4). R4-winning config: 300 blocks.
// ---------------------------------------------------------------------------
__global__ __launch_bounds__(256) void combine_kernel(const float* __restrict__ b2,
                                                      float* __restrict__ out) {
    int i = blockIdx.x * 256 + threadIdx.x;       // over GM*GN/4 = 76800
    float4 r = ((const float4*)b2)[i % (GN / 4)];
#pragma unroll
    for (int z = 0; z < SPLITK; ++z) {
        float4 p = ((const float4*)g_part[z])[i];
        r.x += p.x; r.y += p.y; r.z += p.z; r.w += p.w;
    }
    ((float4*)out)[i] = r;
}

// ---------------------------------------------------------------------------
extern "C" void kernel_launch(void* const* d_in, const int* in_sizes, int n_in,
                              void* d_out, int out_size) {
    const float* wf  = (const float*)d_in[0];   // [4,8192,768] f32
    const int*   ids = (const int*)d_in[1];     // [4,8192] i32
    const float* W2  = (const float*)d_in[2];   // [768,768] f32
    const float* b2  = (const float*)d_in[3];   // [768] f32
    float* out = (float*)d_out;                 // [4,100,768] f32

    init_kernel<<<300, 256>>>(ids);
    pool_kernel<<<TRANS_BLOCKS + POOL_BLOCKS, PBLK>>>(wf, ids, W2);
    gemm_kernel<<<dim3(GM / BMT, GN / BNT, SPLITK), GT>>>();
    combine_kernel<<<300, 256>>>(b2, out);
}

// round 8
// speedup vs baseline: 1.2078x; 1.0977x over previous
#include <cuda_runtime.h>
#include <math_constants.h>
#include <cstdint>

// Problem constants
#define BB 4
#define LL 8192
#define DD 768
#define MAXS 100
#define GM (BB*MAXS)   // 400
#define M2 512         // padded M (rows 400-511 zero)
#define GN DD          // 768
#define GK DD          // 768
#define NK8 (GK/8)     // 96
#define MT (M2/16)     // 32 m-tiles
#define NT (GN/8)      // 96 n-tiles

// pool config
#define TCH 32
#define PBLK 192
#define POOL_BLOCKS ((LL/TCH)*BB)        // 1024

// gemm config
#define SPLITK 6
#define K8_PER_Z (NK8/SPLITK)   // 16
#define NSTAGE 8                // 2 k8 per stage
#define BMT 128                 // 8 mtiles
#define BNT 64                  // 8 ntiles
#define GEMM_THREADS 256

// Scratch (device globals; allocation is forbidden)
__device__ float g_pooled[M2 * GK];            // [512][768] pooled, m-major
__device__ float4 g_afb[NK8 * MT * 32];        // A frags big   [k8][mt][t] float4
__device__ float4 g_afs[NK8 * MT * 32];        // A frags small
__device__ float2 g_bfb[NK8 * NT * 32];        // B frags big   [k8][nt][t] float2
__device__ float2 g_bfs[NK8 * NT * 32];        // B frags small
__device__ float g_part[SPLITK][M2 * GN];      // split-K partials (padded M)

// ---------------------------------------------------------------------------
// helpers
// ---------------------------------------------------------------------------
__device__ __forceinline__ void atomMaxF(float* a, float v) {
    if (v >= 0.0f) atomicMax((int*)a, __float_as_int(v));
    else           atomicMin((unsigned int*)a, __float_as_uint(v));
}
__device__ __forceinline__ void cp_async16(unsigned int smem, const void* gmem) {
    asm volatile("cp.async.cg.shared.global [%0], [%1], 16;\n" :: "r"(smem), "l"(gmem));
}
__device__ __forceinline__ void cp_commit() {
    asm volatile("cp.async.commit_group;\n");
}
template <int N>
__device__ __forceinline__ void cp_wait() {
    asm volatile("cp.async.wait_group %0;\n" :: "n"(N));
}
// round f32 -> tf32 (rna), result as f32 bit pattern
__device__ __forceinline__ float to_tf32(float x) {
    unsigned u;
    asm("cvt.rna.tf32.f32 %0, %1;" : "=r"(u) : "f"(x));
    return __uint_as_float(u);
}
// split x into tf32 big + tf32 small (guard inf so small never NaN)
__device__ __forceinline__ void tf32_split(float x, float& big, float& small) {
    big = to_tf32(x);
    float r = isinf(x) ? 0.0f : x - big;
    small = to_tf32(r);
}
__device__ __forceinline__ void mma_tf32(float4& d, uint4 a, float2 b) {
    asm("mma.sync.aligned.m16n8k8.row.col.f32.tf32.tf32.f32 "
        "{%0,%1,%2,%3}, {%4,%5,%6,%7}, {%8,%9}, {%0,%1,%2,%3};"
        : "+f"(d.x), "+f"(d.y), "+f"(d.z), "+f"(d.w)
        : "r"(a.x), "r"(a.y), "r"(a.z), "r"(a.w),
          "r"(__float_as_uint(b.x)), "r"(__float_as_uint(b.y)));
}

// ---------------------------------------------------------------------------
// Init: g_pooled (m-major): rows <400: -inf on valid slots (s<bb[b]) else 0;
// rows 400-511: 0. 384 blocks x 256, one float4 each.
// ---------------------------------------------------------------------------
__global__ __launch_bounds__(256) void init_kernel(const int* __restrict__ ids) {
    int i4 = blockIdx.x * 256 + threadIdx.x;       // 0..98303
    int flat = i4 * 4;
    int m = flat / DD;                              // same m for all 4 (768%4==0)
    float val = 0.0f;
    if (m < GM) {
        int b = m / MAXS;
        int s = m - b * MAXS;
        int bbmax = __ldg(&ids[b * LL + LL - 1]);
        val = (s < bbmax) ? -CUDART_INF_F : 0.0f;
    }
    ((float4*)g_pooled)[i4] = make_float4(val, val, val, val);
}

// ---------------------------------------------------------------------------
// Pool: token-parallel segment max into g_pooled[m][d]. grid (L/TCH * B).
// ---------------------------------------------------------------------------
__global__ __launch_bounds__(PBLK) void pool_kernel(const float* __restrict__ wf,
                                                    const int* __restrict__ ids) {
    __shared__ int sid[TCH];
    const int pb = blockIdx.x;
    const int b = pb >> 8;                   // 256 chunks per batch
    const int c0 = (pb & 255) * TCH;
    const int tid = threadIdx.x;
    if (tid < TCH) sid[tid] = ids[b * LL + c0 + tid];
    __syncthreads();

    const float4* __restrict__ base =
        (const float4*)(wf + ((size_t)b * LL + c0) * DD) + tid;

    float4 run = make_float4(-CUDART_INF_F, -CUDART_INF_F, -CUDART_INF_F, -CUDART_INF_F);
    int cur = -1;
    const int d0 = tid * 4;

#pragma unroll
    for (int t0 = 0; t0 < TCH; t0 += 8) {
        float4 v[8];
#pragma unroll
        for (int j = 0; j < 8; ++j)
            v[j] = __ldcs(base + (size_t)(t0 + j) * (DD / 4));
#pragma unroll
        for (int j = 0; j < 8; ++j) {
            int id = sid[t0 + j];
            if (id != cur) {
                if (cur > 0) {
                    float* p = g_pooled + (size_t)(b * MAXS + cur - 1) * DD + d0;
                    atomMaxF(p + 0, run.x);
                    atomMaxF(p + 1, run.y);
                    atomMaxF(p + 2, run.z);
                    atomMaxF(p + 3, run.w);
                }
                cur = id;
                run = make_float4(-CUDART_INF_F, -CUDART_INF_F, -CUDART_INF_F, -CUDART_INF_F);
            }
            if (id > 0) {
                run.x = fmaxf(run.x, v[j].x);
                run.y = fmaxf(run.y, v[j].y);
                run.z = fmaxf(run.z, v[j].z);
                run.w = fmaxf(run.w, v[j].w);
            }
        }
    }
    if (cur > 0) {
        float* p = g_pooled + (size_t)(b * MAXS + cur - 1) * DD + d0;
        atomMaxF(p + 0, run.x);
        atomMaxF(p + 1, run.y);
        atomMaxF(p + 2, run.z);
        atomMaxF(p + 3, run.w);
    }
}

// ---------------------------------------------------------------------------
// Convert: split A (pooled) and B (W2) into tf32 big/small pairs, stored in
// exact m16n8k8 mma fragment order so the GEMM does contiguous copies only.
// A frag (a0..a3): (g,c) (g+8,c) (g,c+4) (g+8,c+4);  g=t/4, c=t%4
// B frag (b0,b1):  (k=c, n=g) (k=c+4, n=g)
// ---------------------------------------------------------------------------
#define A_POS (NK8 * MT * 32)   // 98304
#define B_POS (NK8 * NT * 32)   // 294912
__global__ __launch_bounds__(256) void convert_kernel(const float* __restrict__ W2) {
    int i = blockIdx.x * 256 + threadIdx.x;
    if (i < A_POS) {
        int t  = i & 31;
        int mt = (i >> 5) & 31;
        int k8 = i >> 10;
        int g = t >> 2, c = t & 3;
        int r0 = mt * 16 + g, r1 = r0 + 8;
        int k0 = k8 * 8 + c,  k1 = k0 + 4;
        float e0 = g_pooled[r0 * GK + k0];
        float e1 = g_pooled[r1 * GK + k0];
        float e2 = g_pooled[r0 * GK + k1];
        float e3 = g_pooled[r1 * GK + k1];
        float4 bgv, smv;
        tf32_split(e0, bgv.x, smv.x);
        tf32_split(e1, bgv.y, smv.y);
        tf32_split(e2, bgv.z, smv.z);
        tf32_split(e3, bgv.w, smv.w);
        g_afb[i] = bgv;
        g_afs[i] = smv;
    } else {
        int j = i - A_POS;
        if (j >= B_POS) return;
        int t  = j & 31;
        int nt = (j >> 5) % NT;
        int k8 = j / (NT * 32);
        int g = t >> 2, c = t & 3;
        int n  = nt * 8 + g;
        int k0 = k8 * 8 + c, k1 = k0 + 4;
        float e0 = W2[(size_t)n * GK + k0];
        float e1 = W2[(size_t)n * GK + k1];
        float2 bgv, smv;
        tf32_split(e0, bgv.x, smv.x);
        tf32_split(e1, bgv.y, smv.y);
        g_bfb[j] = bgv;
        g_bfs[j] = smv;
    }
}

// ---------------------------------------------------------------------------
// GEMM (3xTF32 tensor cores): part[z] += A @ W2^T over k-chunk z.
// grid (4, 12, 6) = 288 blocks, 256 thr = 8 warps (4 m-warps x 2 n-warps).
// Warp tile 32m x 32n (2 mtiles x 4 ntiles). Double-buffered cp.async of
// fragment-ordered tiles; per k8: 12 LDS + 24 mma.
// ---------------------------------------------------------------------------
__global__ __launch_bounds__(GEMM_THREADS) void gemm_kernel() {
    __shared__ float4 sAf[2][2][2][256];   // [buf][k8][big/sm][mt*32+t] 32KB
    __shared__ float2 sBf[2][2][2][256];   // [buf][k8][big/sm][nt*32+t] 16KB

    const int mb8 = blockIdx.x * 8;        // mtile base
    const int nb8 = blockIdx.y * 8;        // ntile base
    const int z = blockIdx.z;
    const int k8z = z * K8_PER_Z;

    const int tid = threadIdx.x;
    const int lane = tid & 31;
    const int wid = tid >> 5;
    const int mwarp = wid >> 1;            // 0..3
    const int nwarp = wid & 1;             // 0..1

    auto load_stage = [&](int buf, int k8g0) {
#pragma unroll
        for (int kk = 0; kk < 2; ++kk) {
            int k8g = k8g0 + kk;
            const float4* srcAb = g_afb + ((size_t)k8g * MT + mb8) * 32;
            const float4* srcAs = g_afs + ((size_t)k8g * MT + mb8) * 32;
            cp_async16((unsigned int)__cvta_generic_to_shared(&sAf[buf][kk][0][tid]),
                       srcAb + tid);
            cp_async16((unsigned int)__cvta_generic_to_shared(&sAf[buf][kk][1][tid]),
                       srcAs + tid);
            if (tid < 128) {
                const float4* srcBb = (const float4*)(g_bfb + ((size_t)k8g * NT + nb8) * 32);
                const float4* srcBs = (const float4*)(g_bfs + ((size_t)k8g * NT + nb8) * 32);
                cp_async16((unsigned int)__cvta_generic_to_shared(&sBf[buf][kk][0][2 * tid]),
                           srcBb + tid);
                cp_async16((unsigned int)__cvta_generic_to_shared(&sBf[buf][kk][1][2 * tid]),
                           srcBs + tid);
            }
        }
        cp_commit();
    };

    float4 acc[2][4];
#pragma unroll
    for (int i = 0; i < 2; ++i)
#pragma unroll
        for (int j = 0; j < 4; ++j) acc[i][j] = make_float4(0.f, 0.f, 0.f, 0.f);

    load_stage(0, k8z);

    for (int st = 0; st < NSTAGE; ++st) {
        cp_wait<0>();
        __syncthreads();

        if (st + 1 < NSTAGE) load_stage((st + 1) & 1, k8z + (st + 1) * 2);

        const int buf = st & 1;
#pragma unroll
        for (int kk = 0; kk < 2; ++kk) {
            uint4 ab[2], as_[2];
            float2 bbv[4], bsv[4];
#pragma unroll
            for (int i = 0; i < 2; ++i) {
                int mt = mwarp * 2 + i;
                ab[i]  = *(const uint4*)&sAf[buf][kk][0][mt * 32 + lane];
                as_[i] = *(const uint4*)&sAf[buf][kk][1][mt * 32 + lane];
            }
#pragma unroll
            for (int j = 0; j < 4; ++j) {
                int nt = nwarp * 4 + j;
                bbv[j] = sBf[buf][kk][0][nt * 32 + lane];
                bsv[j] = sBf[buf][kk][1][nt * 32 + lane];
            }
#pragma unroll
            for (int i = 0; i < 2; ++i)
#pragma unroll
                for (int j = 0; j < 4; ++j) {
                    mma_tf32(acc[i][j], ab[i], bbv[j]);    // big*big
                    mma_tf32(acc[i][j], ab[i], bsv[j]);    // big*small
                    mma_tf32(acc[i][j], as_[i], bbv[j]);   // small*big
                }
        }
        __syncthreads();
    }

    // epilogue: write D frags to g_part[z] (padded 512 rows)
    float* __restrict__ part = g_part[z];
    const int g = lane >> 2;
    const int c2 = (lane & 3) * 2;
#pragma unroll
    for (int i = 0; i < 2; ++i) {
#pragma unroll
        for (int j = 0; j < 4; ++j) {
            int m0 = mb8 * 16 + mwarp * 32 + i * 16 + g;
            int n0 = nb8 * 8 + nwarp * 32 + j * 8 + c2;
            *(float2*)&part[(size_t)m0 * GN + n0] = make_float2(acc[i][j].x, acc[i][j].y);
            *(float2*)&part[(size_t)(m0 + 8) * GN + n0] = make_float2(acc[i][j].z, acc[i][j].w);
        }
    }
}

// ---------------------------------------------------------------------------
// Combine split-K partials + bias. 600 blocks x 128 thr, 1 float4 each.
// ---------------------------------------------------------------------------
__global__ __launch_bounds__(128) void combine_kernel(const float* __restrict__ b2,
                                                      float* __restrict__ out) {
    int i = blockIdx.x * 128 + threadIdx.x;       // over GM*GN/4 = 76800
    float4 r = ((const float4*)b2)[i % (GN / 4)];
#pragma unroll
    for (int z = 0; z < SPLITK; ++z) {
        float4 p = ((const float4*)g_part[z])[i];   // padding is past row 400
        r.x += p.x; r.y += p.y; r.z += p.z; r.w += p.w;
    }
    ((float4*)out)[i] = r;
}

// ---------------------------------------------------------------------------
extern "C" void kernel_launch(void* const* d_in, const int* in_sizes, int n_in,
                              void* d_out, int out_size) {
    const float* wf  = (const float*)d_in[0];   // [4,8192,768] f32
    const int*   ids = (const int*)d_in[1];     // [4,8192] i32
    const float* W2  = (const float*)d_in[2];   // [768,768] f32
    const float* b2  = (const float*)d_in[3];   // [768] f32
    float* out = (float*)d_out;                 // [4,100,768] f32

    init_kernel<<<384, 256>>>(ids);
    pool_kernel<<<POOL_BLOCKS, PBLK>>>(wf, ids);
    convert_kernel<<<(A_POS + B_POS) / 256, 256>>>(W2);
    gemm_kernel<<<dim3(M2 / BMT, GN / BNT, SPLITK), GEMM_THREADS>>>();
    combine_kernel<<<600, 128>>>(b2, out);
}